// round 2
// baseline (speedup 1.0000x reference)
#include <cuda_runtime.h>
#include <math.h>

#define DD 512
#define SS 256
#define BB 32
#define TT 24
#define NROWS (BB*SS)   // 8192
#define NCTA  128       // persistent scan grid (<= 148 SMs -> all co-resident)

// ---------------- device scratch (static: no runtime allocation) ----------------
__device__ float g_X[NROWS*1024];      // fused [ctx|img] rows, row = b*S+s
__device__ float g_Wcat[512*1024];     // [fc1_w | fc2_w]
__device__ float g_bcat[512];          // fc1_b + fc2_b
__device__ float g_co[NROWS*512];
__device__ float g_codm[NROWS*512];
__device__ float g_qm[TT*BB*512];      // qm projection of all question steps
__device__ float g_r[BB*512];
__device__ float g_add[BB*512];
__device__ float g_trr[BB*512];
__device__ float g_logits[BB*SS];

// grid-barrier state (self-resetting generation barrier; replay-safe)
__device__ unsigned g_barcnt = 0;
__device__ unsigned g_bargen = 0;

// ---------------- helpers ----------------
__device__ __forceinline__ float tanh_fast(float x){
    float ax = fabsf(x);
    float e  = __expf(fminf(ax, 15.0f) * 2.0f);
    float t  = __fdividef(e - 1.0f, e + 1.0f);
    return copysignf(t, x);
}

__device__ __forceinline__ float tanh_mufu(float x){
    float y;
    asm("tanh.approx.f32 %0, %1;" : "=f"(y) : "f"(x));
    return y;
}

__device__ __forceinline__ float warp_sum(float v){
#pragma unroll
    for (int o = 16; o; o >>= 1) v += __shfl_xor_sync(0xffffffffu, v, o);
    return v;
}

__device__ __forceinline__ void grid_bar(){
    __syncthreads();
    if (threadIdx.x == 0){
        __threadfence();
        unsigned gen = *(volatile unsigned*)&g_bargen;
        __threadfence();
        if (atomicAdd(&g_barcnt, 1u) == NCTA - 1u){
            atomicExch(&g_barcnt, 0u);
            __threadfence();
            atomicExch(&g_bargen, gen + 1u);
        } else {
            while (*(volatile unsigned*)&g_bargen == gen) { }
        }
        __threadfence();
    }
    __syncthreads();
}

// ---------------- prep: transpose [S,B,D] -> row-major [(b*S+s), 1024] ----------------
__global__ __launch_bounds__(256) void prep_X(const float* __restrict__ ctx,
                                              const float* __restrict__ img){
    int v   = blockIdx.x * 256 + threadIdx.x;   // exactly NROWS*128 threads
    int row = v >> 7, d4 = v & 127;
    int b   = row >> 8, s = row & 255;
    float4 cv = ((const float4*)ctx)[(s*BB + b)*128 + d4];
    float4 iv = ((const float4*)img)[(s*BB + b)*128 + d4];
    ((float4*)g_X)[row*256 + d4]       = cv;
    ((float4*)g_X)[row*256 + 128 + d4] = iv;
}

__global__ __launch_bounds__(256) void prep_W(const float* __restrict__ fc1w,
                                              const float* __restrict__ fc1b,
                                              const float* __restrict__ fc2w,
                                              const float* __restrict__ fc2b){
    int v = blockIdx.x * 256 + threadIdx.x;     // exactly 512*128 threads
    int n = v >> 7, k4 = v & 127;
    ((float4*)g_Wcat)[n*256 + k4]       = ((const float4*)fc1w)[v];
    ((float4*)g_Wcat)[n*256 + 128 + k4] = ((const float4*)fc2w)[v];
    if (v < 512)    g_bcat[v] = fc1b[v] + fc2b[v];
    if (v < BB*512) g_r[v]    = 0.0f;
}

// ---------------- SGEMM: C[M,N] = A[M,K] * W[N,K]^T + bias[N] ----------------
__global__ __launch_bounds__(256) void sgemm(const float* __restrict__ A,
                                             const float* __restrict__ W,
                                             const float* __restrict__ bias,
                                             float* __restrict__ C,
                                             int M, int N, int K)
{
    __shared__ __align__(16) float As[16*132];
    __shared__ __align__(16) float Bs[16*132];
    const int m0  = blockIdx.y * 128;
    const int n0  = blockIdx.x * 128;
    const int tid = threadIdx.x;
    const int tx  = tid & 15, ty = tid >> 4;
    const int lr0 = tid >> 2;
    const int lc4 = (tid & 3) * 4;

    float acc[8][8] = {};
    const float* Abase = A + (size_t)(m0 + lr0) * K + lc4;
    const float* Wbase = W + (size_t)(n0 + lr0) * K + lc4;

    for (int kt = 0; kt < K; kt += 16){
        float4 a0 = *(const float4*)(Abase + kt);
        float4 a1 = *(const float4*)(Abase + (size_t)64*K + kt);
        float4 w0 = *(const float4*)(Wbase + kt);
        float4 w1 = *(const float4*)(Wbase + (size_t)64*K + kt);
        __syncthreads();
        As[(lc4+0)*132 + lr0]      = a0.x; As[(lc4+1)*132 + lr0]      = a0.y;
        As[(lc4+2)*132 + lr0]      = a0.z; As[(lc4+3)*132 + lr0]      = a0.w;
        As[(lc4+0)*132 + lr0 + 64] = a1.x; As[(lc4+1)*132 + lr0 + 64] = a1.y;
        As[(lc4+2)*132 + lr0 + 64] = a1.z; As[(lc4+3)*132 + lr0 + 64] = a1.w;
        Bs[(lc4+0)*132 + lr0]      = w0.x; Bs[(lc4+1)*132 + lr0]      = w0.y;
        Bs[(lc4+2)*132 + lr0]      = w0.z; Bs[(lc4+3)*132 + lr0]      = w0.w;
        Bs[(lc4+0)*132 + lr0 + 64] = w1.x; Bs[(lc4+1)*132 + lr0 + 64] = w1.y;
        Bs[(lc4+2)*132 + lr0 + 64] = w1.z; Bs[(lc4+3)*132 + lr0 + 64] = w1.w;
        __syncthreads();
#pragma unroll
        for (int k = 0; k < 16; k++){
            float4 af0 = *(const float4*)&As[k*132 + ty*8];
            float4 af1 = *(const float4*)&As[k*132 + ty*8 + 4];
            float4 bf0 = *(const float4*)&Bs[k*132 + tx*8];
            float4 bf1 = *(const float4*)&Bs[k*132 + tx*8 + 4];
            float av[8] = {af0.x,af0.y,af0.z,af0.w,af1.x,af1.y,af1.z,af1.w};
            float bv[8] = {bf0.x,bf0.y,bf0.z,bf0.w,bf1.x,bf1.y,bf1.z,bf1.w};
#pragma unroll
            for (int i = 0; i < 8; i++)
#pragma unroll
                for (int j = 0; j < 8; j++)
                    acc[i][j] = fmaf(av[i], bv[j], acc[i][j]);
        }
    }

    float4 bb0 = *(const float4*)&bias[n0 + tx*8];
    float4 bb1 = *(const float4*)&bias[n0 + tx*8 + 4];
    float bj[8] = {bb0.x,bb0.y,bb0.z,bb0.w,bb1.x,bb1.y,bb1.z,bb1.w};
#pragma unroll
    for (int i = 0; i < 8; i++){
        int m = m0 + ty*8 + i;
        float4 o0 = make_float4(acc[i][0]+bj[0], acc[i][1]+bj[1],
                                acc[i][2]+bj[2], acc[i][3]+bj[3]);
        float4 o1 = make_float4(acc[i][4]+bj[4], acc[i][5]+bj[5],
                                acc[i][6]+bj[6], acc[i][7]+bj[7]);
        *(float4*)&C[(size_t)m*N + n0 + tx*8]     = o0;
        *(float4*)&C[(size_t)m*N + n0 + tx*8 + 4] = o1;
    }
}

// ---------------- persistent scan kernel: the whole T-step loop ----------------
// grid = 128 CTAs x 256 threads. 3 grid barriers / step.
__global__ __launch_bounds__(256) void scan_kernel(
    const float* __restrict__ rm_w, const float* __restrict__ rm_b,
    const float* __restrict__ rr_w, const float* __restrict__ rr_b,
    const float* __restrict__ ms_w, const float* __restrict__ ms_b)
{
    __shared__ __align__(16) float smem[8192];   // 32 KB, reused per phase
    const int tid  = threadIdx.x;
    const int lane = tid & 31;
    const int warp = tid >> 5;
    const int cta  = blockIdx.x;

    // ---- phase-P invariants: this warp owns one weight row across all steps ----
    const int  prow   = cta * 8 + warp;                 // 0..1023
    const bool is_rm  = (prow < 512);
    const int  erow   = is_rm ? prow : (prow - 512);
    const float* wsrc = (is_rm ? rm_w : rr_w) + (size_t)erow * 512;
    float4 w0 = *(const float4*)(wsrc + lane*4);
    float4 w1 = *(const float4*)(wsrc + lane*4 + 128);
    float4 w2 = *(const float4*)(wsrc + lane*4 + 256);
    float4 w3 = *(const float4*)(wsrc + lane*4 + 384);
    const float pbias = is_rm ? rm_b[erow] : rr_b[erow];

    // ---- phase-L/U invariants ----
    const int b_l  = cta >> 2;                          // batch for L and U
    const int s0_l = (cta & 3) * 64;                    // L: s-range start
    const int e0_u = (cta & 3) * 128;                   // U: e-range start
    const float msb0 = ms_b[0];

    for (int t = 0; t < TT; t++){
        // ================= phase P: add = rm(r)+rm_b+qm[t]; trr = tanh(rr(r)+rr_b)
        for (int h = 0; h < 2; h++){
            __syncthreads();
#pragma unroll
            for (int i = 0; i < 8; i++)
                ((float4*)smem)[tid + i*256] = ((const float4*)(g_r + h*8192))[tid + i*256];
            __syncthreads();
#pragma unroll 4
            for (int b16 = 0; b16 < 16; b16++){
                const float* rb = smem + b16*512;
                float4 r0 = *(const float4*)(rb + lane*4);
                float4 r1 = *(const float4*)(rb + lane*4 + 128);
                float4 r2 = *(const float4*)(rb + lane*4 + 256);
                float4 r3 = *(const float4*)(rb + lane*4 + 384);
                float s = w0.x*r0.x + w0.y*r0.y + w0.z*r0.z + w0.w*r0.w
                        + w1.x*r1.x + w1.y*r1.y + w1.z*r1.z + w1.w*r1.w
                        + w2.x*r2.x + w2.y*r2.y + w2.z*r2.z + w2.w*r2.w
                        + w3.x*r3.x + w3.y*r3.y + w3.z*r3.z + w3.w*r3.w;
                s = warp_sum(s);
                if (lane == 0){
                    int b = h*16 + b16;
                    if (is_rm) g_add[b*512 + erow] = s + pbias + g_qm[(t*BB + b)*512 + erow];
                    else       g_trr[b*512 + erow] = tanh_fast(s + pbias);
                }
            }
        }
        grid_bar();

        // ================= phase L: logits[b,s] = sum_e tanh(co_dm+add)*ms_w + ms_b
        {
            smem[tid]        = g_add[b_l*512 + tid];
            smem[tid + 256]  = g_add[b_l*512 + tid + 256];
            smem[tid + 512]  = ms_w[tid];
            smem[tid + 768]  = ms_w[tid + 256];
            __syncthreads();
            const float* sadd = smem;
            const float* smsw = smem + 512;
#pragma unroll
            for (int rw = 0; rw < 8; rw++){
                int s = s0_l + warp*8 + rw;
                const float* cd = g_codm + (size_t)(b_l*256 + s)*512;
                float acc = 0.f;
#pragma unroll
                for (int i = 0; i < 4; i++){
                    int k = lane*4 + i*128;
                    float4 c = *(const float4*)(cd + k);
                    float4 a = *(const float4*)(sadd + k);
                    float4 m = *(const float4*)(smsw + k);
                    acc += tanh_mufu(c.x + a.x) * m.x;
                    acc += tanh_mufu(c.y + a.y) * m.y;
                    acc += tanh_mufu(c.z + a.z) * m.z;
                    acc += tanh_mufu(c.w + a.w) * m.w;
                }
                acc = warp_sum(acc);
                if (lane == 0) g_logits[b_l*256 + s] = acc + msb0;
            }
        }
        grid_bar();

        // ================= phase U: softmax over S + weighted sum of co + trr
        {
            float* sw   = smem;          // [256]
            float* part = smem + 256;    // [256]
            float* red  = smem + 512;    // [8]
            float l = g_logits[b_l*256 + tid];
            float m = l;
#pragma unroll
            for (int o = 16; o; o >>= 1) m = fmaxf(m, __shfl_xor_sync(0xffffffffu, m, o));
            if (lane == 0) red[warp] = m;
            __syncthreads();
            float mx = red[0];
#pragma unroll
            for (int i = 1; i < 8; i++) mx = fmaxf(mx, red[i]);
            float ex = __expf(l - mx);
            float sm = warp_sum(ex);
            __syncthreads();
            if (lane == 0) red[warp] = sm;
            __syncthreads();
            float tot = red[0];
#pragma unroll
            for (int i = 1; i < 8; i++) tot += red[i];
            sw[tid] = ex * (1.0f / tot);
            __syncthreads();

            int e  = e0_u + (tid & 127);
            int sh = tid >> 7;
            const float* cb = g_co + (size_t)(b_l*256 + sh*128)*512 + e;
            const float* wv = sw + sh*128;
            float acc = 0.f;
#pragma unroll 8
            for (int s = 0; s < 128; s++)
                acc = fmaf(wv[s], cb[(size_t)s*512], acc);
            part[tid] = acc;
            __syncthreads();
            if (tid < 128){
                int eo = e0_u + tid;
                g_r[b_l*512 + eo] = part[tid] + part[tid + 128] + g_trr[b_l*512 + eo];
            }
        }
        grid_bar();
    }
}

// ---------------- final: g = rg(r) + qg(qh) ----------------
__global__ __launch_bounds__(256) void final_g(const float* __restrict__ rg_w,
                                               const float* __restrict__ rg_b,
                                               const float* __restrict__ qg_w,
                                               const float* __restrict__ qg_b,
                                               const float* __restrict__ qh,
                                               float* __restrict__ out)
{
    __shared__ __align__(16) float sr[512];
    __shared__ __align__(16) float sq[512];
    int bx  = blockIdx.x;               // 0..2047
    int b   = bx >> 6, ec = bx & 63;
    int tid = threadIdx.x, lane = tid & 31, warp = tid >> 5;
    sr[tid]       = g_r[b*512 + tid];
    sr[tid + 256] = g_r[b*512 + tid + 256];
    sq[tid]       = qh[b*512 + tid];
    sq[tid + 256] = qh[b*512 + tid + 256];
    __syncthreads();
    int e = ec*8 + warp;
    const float* w1 = rg_w + e*512;
    const float* w2 = qg_w + e*512;
    float s = 0.f;
#pragma unroll
    for (int i = 0; i < 4; i++){
        int k = i*128 + lane*4;
        float4 a = *(const float4*)(w1 + k); float4 x = *(const float4*)(sr + k);
        float4 c = *(const float4*)(w2 + k); float4 y = *(const float4*)(sq + k);
        s += a.x*x.x + a.y*x.y + a.z*x.z + a.w*x.w;
        s += c.x*y.x + c.y*y.y + c.z*y.z + c.w*y.w;
    }
    s = warp_sum(s);
    if (lane == 0) out[b*512 + e] = s + rg_b[e] + qg_b[e];
}

// ---------------- host launch ----------------
static float* symaddr(const void* s){
    void* p = nullptr;
    cudaGetSymbolAddress(&p, s);
    return (float*)p;
}

extern "C" void kernel_launch(void* const* d_in, const int* in_sizes, int n_in,
                              void* d_out, int out_size)
{
    const float* ctx  = (const float*)d_in[0];
    const float* qout = (const float*)d_in[2];
    const float* qh   = (const float*)d_in[3];
    const float* img  = (const float*)d_in[4];
    const float* fc1w = (const float*)d_in[6];  const float* fc1b = (const float*)d_in[7];
    const float* fc2w = (const float*)d_in[8];  const float* fc2b = (const float*)d_in[9];
    const float* dmw  = (const float*)d_in[10]; const float* dmb  = (const float*)d_in[11];
    const float* msw  = (const float*)d_in[12]; const float* msb  = (const float*)d_in[13];
    const float* rmw  = (const float*)d_in[14]; const float* rmb  = (const float*)d_in[15];
    const float* qmw  = (const float*)d_in[16]; const float* qmb  = (const float*)d_in[17];
    const float* rrw  = (const float*)d_in[18]; const float* rrb  = (const float*)d_in[19];
    const float* rgw  = (const float*)d_in[20]; const float* rgb  = (const float*)d_in[21];
    const float* qgw  = (const float*)d_in[22]; const float* qgb  = (const float*)d_in[23];

    float* pX    = symaddr(g_X);
    float* pWcat = symaddr(g_Wcat);
    float* pbcat = symaddr(g_bcat);
    float* pco   = symaddr(g_co);
    float* pcodm = symaddr(g_codm);
    float* pqm   = symaddr(g_qm);

    prep_X<<<4096, 256>>>(ctx, img);
    prep_W<<<256, 256>>>(fc1w, fc1b, fc2w, fc2b);

    // co = [ctx|img] @ [fc1|fc2]^T + (fc1_b+fc2_b)
    sgemm<<<dim3(4, 64), 256>>>(pX, pWcat, pbcat, pco, NROWS, 512, 1024);
    // co_dm = co @ dm_w^T + dm_b
    sgemm<<<dim3(4, 64), 256>>>(pco, dmw, dmb, pcodm, NROWS, 512, 512);
    // qm_all = question_output @ qm_w^T + qm_b  (all T steps at once)
    sgemm<<<dim3(4, 6), 256>>>(qout, qmw, qmb, pqm, TT*BB, 512, 512);

    // whole scan in one persistent kernel (3 grid barriers per step)
    scan_kernel<<<NCTA, 256>>>(rmw, rmb, rrw, rrb, msw, msb);

    final_g<<<2048, 256>>>(rgw, rgb, qgw, qgb, qh, (float*)d_out);
}

// round 3
// speedup vs baseline: 1.3410x; 1.3410x over previous
#include <cuda_runtime.h>
#include <math.h>

#define DD 512
#define SS 256
#define BB 32
#define TT 24
#define NROWS (BB*SS)   // 8192

// ---------------- device scratch (static: no runtime allocation) ----------------
__device__ float g_bcat[512];          // fc1_b + fc2_b
__device__ float g_co[NROWS*512];
__device__ float g_codm[NROWS*512];
__device__ float g_qm[TT*BB*512];      // qm projection of all question steps
__device__ float g_r[BB*512];
__device__ float g_add[BB*512];
__device__ float g_trr[BB*512];
__device__ float g_logits[BB*SS];

// ---------------- helpers ----------------
__device__ __forceinline__ float tanh_fast(float x){
    float ax = fabsf(x);
    float e  = __expf(fminf(ax, 15.0f) * 2.0f);
    float t  = __fdividef(e - 1.0f, e + 1.0f);
    return copysignf(t, x);
}

__device__ __forceinline__ float tanh_mufu(float x){
    float y;
    asm("tanh.approx.f32 %0, %1;" : "=f"(y) : "f"(x));
    return y;
}

__device__ __forceinline__ float warp_sum(float v){
#pragma unroll
    for (int o = 16; o; o >>= 1) v += __shfl_xor_sync(0xffffffffu, v, o);
    return v;
}

// ---------------- tiny prep: bias concat + r zero ----------------
__global__ __launch_bounds__(256) void prep_small(const float* __restrict__ fc1b,
                                                  const float* __restrict__ fc2b){
    int v = blockIdx.x * 256 + threadIdx.x;     // 64 blocks = 16384 threads
    if (v < 512)    g_bcat[v] = fc1b[v] + fc2b[v];
    if (v < BB*512) g_r[v]    = 0.0f;
}

// ---------------- fused first GEMM: co = perm(ctx)@fc1^T + perm(img)@fc2^T + bcat
// C row m = b*S+s  <-  source row s*B+b of ctx/img. 128x128 tile, BK=16.
__global__ __launch_bounds__(256) void sgemm12(const float* __restrict__ ctx,
                                               const float* __restrict__ img,
                                               const float* __restrict__ fc1w,
                                               const float* __restrict__ fc2w,
                                               float* __restrict__ C)
{
    __shared__ __align__(16) float As[16*132];
    __shared__ __align__(16) float Bs[16*132];
    const int m0  = blockIdx.y * 128;
    const int n0  = blockIdx.x * 128;
    const int tid = threadIdx.x;
    const int tx  = tid & 15, ty = tid >> 4;
    const int lr0 = tid >> 2;          // 0..63
    const int lc4 = (tid & 3) * 4;     // 0,4,8,12

    // permuted source rows for the two A rows this thread loads
    const int r1 = m0 + lr0,      r2 = r1 + 64;
    const int p1 = (r1 & 255)*32 + (r1 >> 8);
    const int p2 = (r2 & 255)*32 + (r2 >> 8);

    float acc[8][8] = {};

#pragma unroll 1
    for (int half = 0; half < 2; half++){
        const float* Asrc = half ? img  : ctx;
        const float* Wsrc = half ? fc2w : fc1w;
        const float* A1 = Asrc + (size_t)p1*512 + lc4;
        const float* A2 = Asrc + (size_t)p2*512 + lc4;
        const float* W1 = Wsrc + (size_t)(n0 + lr0)*512 + lc4;
        const float* W2 = Wsrc + (size_t)(n0 + lr0 + 64)*512 + lc4;
        for (int kt = 0; kt < 512; kt += 16){
            float4 a0 = *(const float4*)(A1 + kt);
            float4 a1 = *(const float4*)(A2 + kt);
            float4 w0 = *(const float4*)(W1 + kt);
            float4 w1 = *(const float4*)(W2 + kt);
            __syncthreads();
            As[(lc4+0)*132 + lr0]      = a0.x; As[(lc4+1)*132 + lr0]      = a0.y;
            As[(lc4+2)*132 + lr0]      = a0.z; As[(lc4+3)*132 + lr0]      = a0.w;
            As[(lc4+0)*132 + lr0 + 64] = a1.x; As[(lc4+1)*132 + lr0 + 64] = a1.y;
            As[(lc4+2)*132 + lr0 + 64] = a1.z; As[(lc4+3)*132 + lr0 + 64] = a1.w;
            Bs[(lc4+0)*132 + lr0]      = w0.x; Bs[(lc4+1)*132 + lr0]      = w0.y;
            Bs[(lc4+2)*132 + lr0]      = w0.z; Bs[(lc4+3)*132 + lr0]      = w0.w;
            Bs[(lc4+0)*132 + lr0 + 64] = w1.x; Bs[(lc4+1)*132 + lr0 + 64] = w1.y;
            Bs[(lc4+2)*132 + lr0 + 64] = w1.z; Bs[(lc4+3)*132 + lr0 + 64] = w1.w;
            __syncthreads();
#pragma unroll
            for (int k = 0; k < 16; k++){
                float4 af0 = *(const float4*)&As[k*132 + ty*8];
                float4 af1 = *(const float4*)&As[k*132 + ty*8 + 4];
                float4 bf0 = *(const float4*)&Bs[k*132 + tx*8];
                float4 bf1 = *(const float4*)&Bs[k*132 + tx*8 + 4];
                float av[8] = {af0.x,af0.y,af0.z,af0.w,af1.x,af1.y,af1.z,af1.w};
                float bv[8] = {bf0.x,bf0.y,bf0.z,bf0.w,bf1.x,bf1.y,bf1.z,bf1.w};
#pragma unroll
                for (int i = 0; i < 8; i++)
#pragma unroll
                    for (int j = 0; j < 8; j++)
                        acc[i][j] = fmaf(av[i], bv[j], acc[i][j]);
            }
        }
    }

    float4 bb0 = *(const float4*)&g_bcat[n0 + tx*8];
    float4 bb1 = *(const float4*)&g_bcat[n0 + tx*8 + 4];
    float bj[8] = {bb0.x,bb0.y,bb0.z,bb0.w,bb1.x,bb1.y,bb1.z,bb1.w};
#pragma unroll
    for (int i = 0; i < 8; i++){
        int m = m0 + ty*8 + i;
        float4 o0 = make_float4(acc[i][0]+bj[0], acc[i][1]+bj[1],
                                acc[i][2]+bj[2], acc[i][3]+bj[3]);
        float4 o1 = make_float4(acc[i][4]+bj[4], acc[i][5]+bj[5],
                                acc[i][6]+bj[6], acc[i][7]+bj[7]);
        *(float4*)&C[(size_t)m*512 + n0 + tx*8]     = o0;
        *(float4*)&C[(size_t)m*512 + n0 + tx*8 + 4] = o1;
    }
}

// ---------------- generic SGEMM: C[M,N] = A[M,K] * W[N,K]^T + bias[N] ----------------
__global__ __launch_bounds__(256) void sgemm(const float* __restrict__ A,
                                             const float* __restrict__ W,
                                             const float* __restrict__ bias,
                                             float* __restrict__ C,
                                             int M, int N, int K)
{
    __shared__ __align__(16) float As[16*132];
    __shared__ __align__(16) float Bs[16*132];
    const int m0  = blockIdx.y * 128;
    const int n0  = blockIdx.x * 128;
    const int tid = threadIdx.x;
    const int tx  = tid & 15, ty = tid >> 4;
    const int lr0 = tid >> 2;
    const int lc4 = (tid & 3) * 4;

    float acc[8][8] = {};
    const float* Abase = A + (size_t)(m0 + lr0) * K + lc4;
    const float* Wbase = W + (size_t)(n0 + lr0) * K + lc4;

    for (int kt = 0; kt < K; kt += 16){
        float4 a0 = *(const float4*)(Abase + kt);
        float4 a1 = *(const float4*)(Abase + (size_t)64*K + kt);
        float4 w0 = *(const float4*)(Wbase + kt);
        float4 w1 = *(const float4*)(Wbase + (size_t)64*K + kt);
        __syncthreads();
        As[(lc4+0)*132 + lr0]      = a0.x; As[(lc4+1)*132 + lr0]      = a0.y;
        As[(lc4+2)*132 + lr0]      = a0.z; As[(lc4+3)*132 + lr0]      = a0.w;
        As[(lc4+0)*132 + lr0 + 64] = a1.x; As[(lc4+1)*132 + lr0 + 64] = a1.y;
        As[(lc4+2)*132 + lr0 + 64] = a1.z; As[(lc4+3)*132 + lr0 + 64] = a1.w;
        Bs[(lc4+0)*132 + lr0]      = w0.x; Bs[(lc4+1)*132 + lr0]      = w0.y;
        Bs[(lc4+2)*132 + lr0]      = w0.z; Bs[(lc4+3)*132 + lr0]      = w0.w;
        Bs[(lc4+0)*132 + lr0 + 64] = w1.x; Bs[(lc4+1)*132 + lr0 + 64] = w1.y;
        Bs[(lc4+2)*132 + lr0 + 64] = w1.z; Bs[(lc4+3)*132 + lr0 + 64] = w1.w;
        __syncthreads();
#pragma unroll
        for (int k = 0; k < 16; k++){
            float4 af0 = *(const float4*)&As[k*132 + ty*8];
            float4 af1 = *(const float4*)&As[k*132 + ty*8 + 4];
            float4 bf0 = *(const float4*)&Bs[k*132 + tx*8];
            float4 bf1 = *(const float4*)&Bs[k*132 + tx*8 + 4];
            float av[8] = {af0.x,af0.y,af0.z,af0.w,af1.x,af1.y,af1.z,af1.w};
            float bv[8] = {bf0.x,bf0.y,bf0.z,bf0.w,bf1.x,bf1.y,bf1.z,bf1.w};
#pragma unroll
            for (int i = 0; i < 8; i++)
#pragma unroll
                for (int j = 0; j < 8; j++)
                    acc[i][j] = fmaf(av[i], bv[j], acc[i][j]);
        }
    }

    float4 bb0 = *(const float4*)&bias[n0 + tx*8];
    float4 bb1 = *(const float4*)&bias[n0 + tx*8 + 4];
    float bj[8] = {bb0.x,bb0.y,bb0.z,bb0.w,bb1.x,bb1.y,bb1.z,bb1.w};
#pragma unroll
    for (int i = 0; i < 8; i++){
        int m = m0 + ty*8 + i;
        float4 o0 = make_float4(acc[i][0]+bj[0], acc[i][1]+bj[1],
                                acc[i][2]+bj[2], acc[i][3]+bj[3]);
        float4 o1 = make_float4(acc[i][4]+bj[4], acc[i][5]+bj[5],
                                acc[i][6]+bj[6], acc[i][7]+bj[7]);
        *(float4*)&C[(size_t)m*N + n0 + tx*8]     = o0;
        *(float4*)&C[(size_t)m*N + n0 + tx*8 + 4] = o1;
    }
}

// ---------------- per-step kernel 1: add = rm(r)+rm_b+qm[t]; trr = tanh(rr(r)+rr_b) ----------------
__global__ __launch_bounds__(256) void step_proj(const float* __restrict__ rm_w,
                                                 const float* __restrict__ rm_b,
                                                 const float* __restrict__ rr_w,
                                                 const float* __restrict__ rr_b,
                                                 int t)
{
    __shared__ __align__(16) float sr[512];
    int bx   = blockIdx.x;
    int mat  = bx >> 11;
    int b    = (bx >> 6) & 31;
    int ec   = bx & 63;
    int tid  = threadIdx.x, lane = tid & 31, warp = tid >> 5;
    sr[tid]       = g_r[b*512 + tid];
    sr[tid + 256] = g_r[b*512 + tid + 256];
    __syncthreads();
    int e = ec*8 + warp;
    const float* wrow = (mat ? rr_w : rm_w) + e*512;
    float s = 0.f;
#pragma unroll
    for (int i = 0; i < 4; i++){
        int k = i*128 + lane*4;
        float4 w4 = *(const float4*)(wrow + k);
        float4 r4 = *(const float4*)(sr + k);
        s += w4.x*r4.x + w4.y*r4.y + w4.z*r4.z + w4.w*r4.w;
    }
    s = warp_sum(s);
    if (lane == 0){
        if (mat == 0) g_add[b*512 + e] = s + rm_b[e] + g_qm[(t*BB + b)*512 + e];
        else          g_trr[b*512 + e] = tanh_fast(s + rr_b[e]);
    }
}

// ---------------- per-step kernel 2: logits[b,s] = sum_e tanh(co_dm+add)*ms_w + ms_b ----------------
// 1024 blocks x 256 thr; add & ms_w staged in smem; warp per (b,s) row.
__global__ __launch_bounds__(256) void step_logits(const float* __restrict__ ms_w,
                                                   const float* __restrict__ ms_b){
    __shared__ __align__(16) float sadd[512];
    __shared__ __align__(16) float smw[512];
    int tid  = threadIdx.x, lane = tid & 31, warp = tid >> 5;
    int b    = blockIdx.x >> 5;
    int row  = blockIdx.x*8 + warp;          // global (b,s) row; 8 rows per block
    sadd[tid]       = g_add[b*512 + tid];
    sadd[tid + 256] = g_add[b*512 + tid + 256];
    smw[tid]        = ms_w[tid];
    smw[tid + 256]  = ms_w[tid + 256];
    __syncthreads();
    const float* cd = g_codm + (size_t)row*512;
    float s = 0.f;
#pragma unroll
    for (int i = 0; i < 4; i++){
        int k = i*128 + lane*4;
        float4 c = *(const float4*)(cd + k);
        float4 a = *(const float4*)(sadd + k);
        float4 m = *(const float4*)(smw + k);
        s += tanh_mufu(c.x + a.x) * m.x;
        s += tanh_mufu(c.y + a.y) * m.y;
        s += tanh_mufu(c.z + a.z) * m.z;
        s += tanh_mufu(c.w + a.w) * m.w;
    }
    s = warp_sum(s);
    if (lane == 0) g_logits[row] = s + ms_b[0];
}

// ---------------- per-step kernel 3: softmax over S + weighted sum of co + trr ----------------
// grid (32 b, 8 e-chunks of 64) x 256 thr; S split 4-way per thread.
__global__ __launch_bounds__(256) void step_update(){
    __shared__ float sw[256];
    __shared__ float part[256];
    __shared__ float red[16];
    int b = blockIdx.x, ec = blockIdx.y, tid = threadIdx.x;
    int lane = tid & 31, warp = tid >> 5;

    float l = g_logits[b*256 + tid];
    float m = l;
#pragma unroll
    for (int o = 16; o; o >>= 1) m = fmaxf(m, __shfl_xor_sync(0xffffffffu, m, o));
    if (lane == 0) red[warp] = m;
    __syncthreads();
    float mx = red[0];
#pragma unroll
    for (int i = 1; i < 8; i++) mx = fmaxf(mx, red[i]);
    float ex = __expf(l - mx);
    float sm = warp_sum(ex);
    if (lane == 0) red[8 + warp] = sm;
    __syncthreads();
    float tot = red[8];
#pragma unroll
    for (int i = 9; i < 16; i++) tot += red[i];
    sw[tid] = ex * (1.0f / tot);
    __syncthreads();

    int e  = ec*64 + (tid & 63);
    int sq = tid >> 6;                       // 0..3, 64 s each
    const float* cb = g_co + (size_t)(b*256 + sq*64)*512 + e;
    const float* wv = sw + sq*64;
    float acc = 0.f;
#pragma unroll 8
    for (int s = 0; s < 64; s++)
        acc = fmaf(wv[s], cb[(size_t)s*512], acc);
    part[tid] = acc;
    __syncthreads();
    if (tid < 64){
        int eo = ec*64 + tid;
        g_r[b*512 + eo] = part[tid] + part[tid+64] + part[tid+128] + part[tid+192]
                        + g_trr[b*512 + eo];
    }
}

// ---------------- final: g = rg(r) + qg(qh) ----------------
__global__ __launch_bounds__(256) void final_g(const float* __restrict__ rg_w,
                                               const float* __restrict__ rg_b,
                                               const float* __restrict__ qg_w,
                                               const float* __restrict__ qg_b,
                                               const float* __restrict__ qh,
                                               float* __restrict__ out)
{
    __shared__ __align__(16) float sr[512];
    __shared__ __align__(16) float sq[512];
    int bx  = blockIdx.x;               // 0..2047
    int b   = bx >> 6, ec = bx & 63;
    int tid = threadIdx.x, lane = tid & 31, warp = tid >> 5;
    sr[tid]       = g_r[b*512 + tid];
    sr[tid + 256] = g_r[b*512 + tid + 256];
    sq[tid]       = qh[b*512 + tid];
    sq[tid + 256] = qh[b*512 + tid + 256];
    __syncthreads();
    int e = ec*8 + warp;
    const float* w1 = rg_w + e*512;
    const float* w2 = qg_w + e*512;
    float s = 0.f;
#pragma unroll
    for (int i = 0; i < 4; i++){
        int k = i*128 + lane*4;
        float4 a = *(const float4*)(w1 + k); float4 x = *(const float4*)(sr + k);
        float4 c = *(const float4*)(w2 + k); float4 y = *(const float4*)(sq + k);
        s += a.x*x.x + a.y*x.y + a.z*x.z + a.w*x.w;
        s += c.x*y.x + c.y*y.y + c.z*y.z + c.w*y.w;
    }
    s = warp_sum(s);
    if (lane == 0) out[b*512 + e] = s + rg_b[e] + qg_b[e];
}

// ---------------- host launch ----------------
static float* symaddr(const void* s){
    void* p = nullptr;
    cudaGetSymbolAddress(&p, s);
    return (float*)p;
}

extern "C" void kernel_launch(void* const* d_in, const int* in_sizes, int n_in,
                              void* d_out, int out_size)
{
    const float* ctx  = (const float*)d_in[0];
    const float* qout = (const float*)d_in[2];
    const float* qh   = (const float*)d_in[3];
    const float* img  = (const float*)d_in[4];
    const float* fc1w = (const float*)d_in[6];  const float* fc1b = (const float*)d_in[7];
    const float* fc2w = (const float*)d_in[8];  const float* fc2b = (const float*)d_in[9];
    const float* dmw  = (const float*)d_in[10]; const float* dmb  = (const float*)d_in[11];
    const float* msw  = (const float*)d_in[12]; const float* msb  = (const float*)d_in[13];
    const float* rmw  = (const float*)d_in[14]; const float* rmb  = (const float*)d_in[15];
    const float* qmw  = (const float*)d_in[16]; const float* qmb  = (const float*)d_in[17];
    const float* rrw  = (const float*)d_in[18]; const float* rrb  = (const float*)d_in[19];
    const float* rgw  = (const float*)d_in[20]; const float* rgb  = (const float*)d_in[21];
    const float* qgw  = (const float*)d_in[22]; const float* qgb  = (const float*)d_in[23];

    float* pco   = symaddr(g_co);
    float* pcodm = symaddr(g_codm);
    float* pqm   = symaddr(g_qm);

    prep_small<<<64, 256>>>(fc1b, fc2b);

    // co = perm(ctx)@fc1^T + perm(img)@fc2^T + (fc1_b+fc2_b)   (no transpose pass)
    sgemm12<<<dim3(4, 64), 256>>>(ctx, img, fc1w, fc2w, pco);
    // co_dm = co @ dm_w^T + dm_b
    sgemm<<<dim3(4, 64), 256>>>(pco, dmw, dmb, pcodm, NROWS, 512, 512);
    // qm_all = question_output @ qm_w^T + qm_b  (all T steps at once)
    sgemm<<<dim3(4, 6), 256>>>(qout, qmw, qmb, pqm, TT*BB, 512, 512);

    for (int t = 0; t < TT; t++){
        step_proj<<<4096, 256>>>(rmw, rmb, rrw, rrb, t);
        step_logits<<<1024, 256>>>(msw, msb);
        step_update<<<dim3(32, 8), 256>>>();
    }

    final_g<<<2048, 256>>>(rgw, rgb, qgw, qgb, qh, (float*)d_out);
}